// round 5
// baseline (speedup 1.0000x reference)
#include <cuda_runtime.h>
#include <cstdint>
#include <cstddef>

typedef unsigned long long ull;

#define KD    9
#define PADV  4
#define BATCH 2
#define CCH   64
#define HH    32
#define WW    32
#define DD    32
#define TW    4
#define NTHR  160
#define NACT  144

// smem layout (floats):
//   in1 tile: [c][w][d]   stride 34 (32 data + 2 bank pad)       -> conflict-free
//   in2 halo: [c][row][d'] stride 42 (4 zero | 32 data | 4 zero | 2 pad)
#define IN1_STRIDE 34
#define IN1_FLOATS (CCH*TW*IN1_STRIDE)            // 8704
#define IN2_ROWS   12
#define IN2_STRIDE 42
#define IN2_FLOATS (CCH*IN2_ROWS*IN2_STRIDE)      // 32256
#define SMEM_BYTES ((IN1_FLOATS + IN2_FLOATS)*4)  // 163840 bytes

__device__ __forceinline__ ull pack2f(float lo, float hi) {
    ull r;
    asm("mov.b64 %0, {%1, %2};" : "=l"(r) : "f"(lo), "f"(hi));
    return r;
}
// packed f32x2 FMA: d = a*b + d  (FFMA2; only reachable via PTX)
__device__ __forceinline__ void ffma2(ull& d, ull a, ull b) {
    asm("fma.rn.f32x2 %0, %1, %2, %0;" : "+l"(d) : "l"(a), "l"(b));
}

__global__ void __launch_bounds__(NTHR, 1)
corr3d_kernel(const float* __restrict__ in1, const float* __restrict__ in2,
              float* __restrict__ out)
{
    extern __shared__ float sm[];
    float* s1 = sm;               // in1 tile
    float* s2 = sm + IN1_FLOATS;  // in2 halo rows

    const int tid = threadIdx.x;
    const int w0  = blockIdx.x * TW;
    const int h   = blockIdx.y;
    const int b   = blockIdx.z;

    // Zero the in2 buffer once: d-edge pads and OOB-w rows stay zero forever.
    for (int i = tid; i < IN2_FLOATS; i += NTHR) s2[i] = 0.0f;

    // Stage in1 tile: 64c x 4w x 8 float4
    for (int i = tid; i < CCH*TW*8; i += NTHR) {
        int j  = i & 7;
        int rw = i >> 3;
        int c  = rw >> 2;
        int w  = rw & 3;
        const float4 v = *reinterpret_cast<const float4*>(
            in1 + ((((size_t)b*CCH + c)*HH + h)*WW + (w0 + w))*DD + j*4);
        float2* dst = reinterpret_cast<float2*>(s1 + (c*TW + w)*IN1_STRIDE + j*4);
        dst[0] = make_float2(v.x, v.y);
        dst[1] = make_float2(v.z, v.w);
    }

    const int dx  = tid >> 4;        // 0..8 (tid<144)
    const int wl  = (tid >> 2) & 3;  // 0..3
    const int dbk = tid & 3;         // 0..3
    const int d0  = dbk << 3;        // 0,8,16,24
    const int row = wl + dx;         // in2 halo row index 0..11
    const bool active = (tid < NACT);

    for (int dy = 0; dy < KD; ++dy) {
        ull acc[KD][4];
        #pragma unroll
        for (int z = 0; z < KD; ++z) {
            #pragma unroll
            for (int j = 0; j < 4; ++j) acc[z][j] = 0ULL;
        }

        const int hp = h + dy - PADV;           // uniform across block
        if ((unsigned)hp < (unsigned)HH) {
            __syncthreads();  // previous dy's compute (and init) done before restaging

            // Stage 12 in2 rows at h'=hp: 64c x 12rows x 8 float4
            for (int i = tid; i < CCH*IN2_ROWS*8; i += NTHR) {
                int j  = i & 7;
                int rr = i >> 3;
                int c  = rr / IN2_ROWS;
                int r  = rr - c*IN2_ROWS;
                int wp = w0 + r - PADV;
                if ((unsigned)wp < (unsigned)WW) {
                    const float4 v = *reinterpret_cast<const float4*>(
                        in2 + ((((size_t)b*CCH + c)*HH + hp)*WW + wp)*DD + j*4);
                    float2* dst = reinterpret_cast<float2*>(
                        s2 + (c*IN2_ROWS + r)*IN2_STRIDE + 4 + j*4);
                    dst[0] = make_float2(v.x, v.y);
                    dst[1] = make_float2(v.z, v.w);
                }
            }
            __syncthreads();

            if (active) {
                const ull* p1 = reinterpret_cast<const ull*>(s1)
                                + wl*(IN1_STRIDE/2) + (d0 >> 1);
                const ull* p2 = reinterpret_cast<const ull*>(s2)
                                + row*(IN2_STRIDE/2) + (d0 >> 1);
                #pragma unroll 2
                for (int c = 0; c < CCH; ++c) {
                    ull A[4], V[8], OV[7];
                    #pragma unroll
                    for (int j = 0; j < 4; ++j) A[j] = p1[j];   // in1 pairs (d0+2j, d0+2j+1)
                    #pragma unroll
                    for (int m = 0; m < 8; ++m) V[m] = p2[m];   // in2 pairs covering d0..d0+15
                    // odd-aligned pairs: OV[m] = (v[2m+1], v[2m+2])
                    #pragma unroll
                    for (int m = 0; m < 7; ++m) {
                        float a = __uint_as_float((unsigned)(V[m]   >> 32));
                        float c2 = __uint_as_float((unsigned)(V[m+1] & 0xFFFFFFFFu));
                        OV[m] = pack2f(a, c2);
                    }
                    #pragma unroll
                    for (int dz = 0; dz < KD; ++dz) {
                        #pragma unroll
                        for (int j = 0; j < 4; ++j) {
                            ull bb = (dz & 1) ? OV[((dz - 1) >> 1) + j]
                                              : V[(dz >> 1) + j];
                            ffma2(acc[dz][j], bb, A[j]);
                        }
                    }
                    p1 += TW * (IN1_STRIDE/2);        // 68 pairs per channel
                    p2 += IN2_ROWS * (IN2_STRIDE/2);  // 252 pairs per channel
                }
            }
        }
        // write (zeros if hp was out of range — output buffer is poisoned)
        if (active) {
            const int kbase = (dy*KD + dx)*KD;
            float* op = out + (((size_t)b*(KD*KD*KD) + kbase)*HH + h)*(WW*DD)
                            + (w0 + wl)*DD + d0;
            #pragma unroll
            for (int dz = 0; dz < KD; ++dz) {
                ulonglong2 v0; v0.x = acc[dz][0]; v0.y = acc[dz][1];
                ulonglong2 v1; v1.x = acc[dz][2]; v1.y = acc[dz][3];
                *reinterpret_cast<ulonglong2*>(op)     = v0;
                *reinterpret_cast<ulonglong2*>(op + 4) = v1;
                op += (size_t)HH * WW * DD;   // next dz channel
            }
        }
    }
}

extern "C" void kernel_launch(void* const* d_in, const int* in_sizes, int n_in,
                              void* d_out, int out_size)
{
    const float* in1 = (const float*)d_in[0];
    const float* in2 = (const float*)d_in[1];
    float* out = (float*)d_out;

    cudaFuncSetAttribute(corr3d_kernel,
                         cudaFuncAttributeMaxDynamicSharedMemorySize, SMEM_BYTES);

    dim3 grid(WW / TW, HH, BATCH);   // 8 x 32 x 2 = 512 blocks
    corr3d_kernel<<<grid, NTHR, SMEM_BYTES>>>(in1, in2, out);
}

// round 6
// speedup vs baseline: 1.3984x; 1.3984x over previous
#include <cuda_runtime.h>
#include <cstdint>
#include <cstddef>

typedef unsigned long long ull;

#define KD    9
#define PADV  4
#define BATCH 2
#define CCH   64
#define HH    32
#define WW    32
#define DD    32
#define TW    4
#define NTHR  160
#define NACT  144

#define CCHUNK 16
#define NCHUNK (CCH / CCHUNK)   // 4

// smem layout (floats):
//   in1 tile: [c][w][d]        stride 34 (32 data + 2 pad), all 64 channels resident
//   in2 halo: [cc][row][d']    stride 42 (4 zero | 32 data | 4 zero | 2 pad), 16-channel chunk
#define IN1_STRIDE 34
#define IN1_FLOATS (CCH*TW*IN1_STRIDE)                 // 8704  (34816 B)
#define IN2_ROWS   12
#define IN2_STRIDE 42
#define IN2_FLOATS (CCHUNK*IN2_ROWS*IN2_STRIDE)        // 8064  (32256 B)
#define SMEM_BYTES ((IN1_FLOATS + IN2_FLOATS)*4)       // 67072 B -> 3 CTAs/SM

__device__ __forceinline__ ull pack2f(float lo, float hi) {
    ull r;
    asm("mov.b64 %0, {%1, %2};" : "=l"(r) : "f"(lo), "f"(hi));
    return r;
}
// packed f32x2 FMA: d = a*b + d  (FFMA2; only reachable via PTX)
__device__ __forceinline__ void ffma2(ull& d, ull a, ull b) {
    asm("fma.rn.f32x2 %0, %1, %2, %0;" : "+l"(d) : "l"(a), "l"(b));
}

__global__ void __launch_bounds__(NTHR, 3)
corr3d_kernel(const float* __restrict__ in1, const float* __restrict__ in2,
              float* __restrict__ out)
{
    extern __shared__ float sm[];
    float* s1 = sm;               // in1 tile (all channels)
    float* s2 = sm + IN1_FLOATS;  // in2 halo rows (one 16-channel chunk)

    const int tid = threadIdx.x;
    const int w0  = blockIdx.x * TW;
    const int h   = blockIdx.y;
    const int b   = blockIdx.z;

    // Zero the in2 chunk buffer once: d-edge pads and OOB-w rows stay zero
    // forever (every chunk re-writes exactly the same valid-cell pattern).
    for (int i = tid; i < IN2_FLOATS; i += NTHR) s2[i] = 0.0f;

    // Stage full in1 tile: 64c x 4w x 8 float4
    for (int i = tid; i < CCH*TW*8; i += NTHR) {
        int j  = i & 7;
        int rw = i >> 3;
        int c  = rw >> 2;
        int w  = rw & 3;
        const float4 v = *reinterpret_cast<const float4*>(
            in1 + ((((size_t)b*CCH + c)*HH + h)*WW + (w0 + w))*DD + j*4);
        float2* dst = reinterpret_cast<float2*>(s1 + (c*TW + w)*IN1_STRIDE + j*4);
        dst[0] = make_float2(v.x, v.y);
        dst[1] = make_float2(v.z, v.w);
    }

    const int dx  = tid >> 4;        // 0..8 (tid<144)
    const int wl  = (tid >> 2) & 3;  // 0..3
    const int dbk = tid & 3;         // 0..3
    const int d0  = dbk << 3;        // 0,8,16,24
    const int row = wl + dx;         // in2 halo row index 0..11
    const bool active = (tid < NACT);

    for (int dy = 0; dy < KD; ++dy) {
        ull acc[KD][4];
        #pragma unroll
        for (int z = 0; z < KD; ++z) {
            #pragma unroll
            for (int j = 0; j < 4; ++j) acc[z][j] = 0ULL;
        }

        const int hp = h + dy - PADV;           // uniform across block
        if ((unsigned)hp < (unsigned)HH) {
            for (int ck = 0; ck < NCHUNK; ++ck) {
                // wait for previous compute (or init) before re-staging buffer
                __syncthreads();

                // Stage 16 channels x 12 in2 rows at h'=hp
                for (int i = tid; i < CCHUNK*IN2_ROWS*8; i += NTHR) {
                    int j  = i & 7;
                    int rr = i >> 3;
                    int cl = rr / IN2_ROWS;
                    int r  = rr - cl*IN2_ROWS;
                    int wp = w0 + r - PADV;
                    if ((unsigned)wp < (unsigned)WW) {
                        int c = ck*CCHUNK + cl;
                        const float4 v = *reinterpret_cast<const float4*>(
                            in2 + ((((size_t)b*CCH + c)*HH + hp)*WW + wp)*DD + j*4);
                        float2* dst = reinterpret_cast<float2*>(
                            s2 + (cl*IN2_ROWS + r)*IN2_STRIDE + 4 + j*4);
                        dst[0] = make_float2(v.x, v.y);
                        dst[1] = make_float2(v.z, v.w);
                    }
                }
                __syncthreads();

                if (active) {
                    const ull* p1 = reinterpret_cast<const ull*>(s1)
                                    + (ck*CCHUNK*TW + wl)*(IN1_STRIDE/2) + (d0 >> 1);
                    const ull* p2 = reinterpret_cast<const ull*>(s2)
                                    + row*(IN2_STRIDE/2) + (d0 >> 1);
                    #pragma unroll 2
                    for (int c = 0; c < CCHUNK; ++c) {
                        ull A[4], V[8], OV[7];
                        #pragma unroll
                        for (int j = 0; j < 4; ++j) A[j] = p1[j];   // in1 pairs
                        #pragma unroll
                        for (int m = 0; m < 8; ++m) V[m] = p2[m];   // in2 pairs d0..d0+15
                        // odd-aligned pairs: OV[m] = (v[2m+1], v[2m+2])
                        #pragma unroll
                        for (int m = 0; m < 7; ++m) {
                            float a  = __uint_as_float((unsigned)(V[m]   >> 32));
                            float c2 = __uint_as_float((unsigned)(V[m+1] & 0xFFFFFFFFu));
                            OV[m] = pack2f(a, c2);
                        }
                        #pragma unroll
                        for (int dz = 0; dz < KD; ++dz) {
                            #pragma unroll
                            for (int j = 0; j < 4; ++j) {
                                ull bb = (dz & 1) ? OV[((dz - 1) >> 1) + j]
                                                  : V[(dz >> 1) + j];
                                ffma2(acc[dz][j], bb, A[j]);
                            }
                        }
                        p1 += TW * (IN1_STRIDE/2);        // 68 pairs per channel
                        p2 += IN2_ROWS * (IN2_STRIDE/2);  // 252 pairs per channel
                    }
                }
            }
        }
        // write (zeros if hp was out of range — output buffer is poisoned)
        if (active) {
            const int kbase = (dy*KD + dx)*KD;
            float* op = out + (((size_t)b*(KD*KD*KD) + kbase)*HH + h)*(WW*DD)
                            + (w0 + wl)*DD + d0;
            #pragma unroll
            for (int dz = 0; dz < KD; ++dz) {
                ulonglong2 v0; v0.x = acc[dz][0]; v0.y = acc[dz][1];
                ulonglong2 v1; v1.x = acc[dz][2]; v1.y = acc[dz][3];
                *reinterpret_cast<ulonglong2*>(op)     = v0;
                *reinterpret_cast<ulonglong2*>(op + 4) = v1;
                op += (size_t)HH * WW * DD;   // next dz channel
            }
        }
    }
}

extern "C" void kernel_launch(void* const* d_in, const int* in_sizes, int n_in,
                              void* d_out, int out_size)
{
    const float* in1 = (const float*)d_in[0];
    const float* in2 = (const float*)d_in[1];
    float* out = (float*)d_out;

    cudaFuncSetAttribute(corr3d_kernel,
                         cudaFuncAttributeMaxDynamicSharedMemorySize, SMEM_BYTES);

    dim3 grid(WW / TW, HH, BATCH);   // 8 x 32 x 2 = 512 blocks
    corr3d_kernel<<<grid, NTHR, SMEM_BYTES>>>(in1, in2, out);
}